// round 3
// baseline (speedup 1.0000x reference)
#include <cuda_runtime.h>

#define H 512
#define W 512
#define NIMG 48
#define ROWS 16
#define CPT 8                                   // output columns per thread
#define STRIPS_X (W / CPT)                      // 64
#define STRIPS_Y (H / ROWS)                     // 32
#define THREADS_PER_IMG (STRIPS_X * STRIPS_Y)   // 2048
#define BLOCK 256

__device__ __forceinline__ float med3f(float a, float b, float c) {
    // median of 3 with 4 min/max ops
    return fmaxf(fminf(a, b), fminf(fmaxf(a, b), c));
}

// Load row[c0-1 .. c0+8] into d[0..9] with reflect at the image borders.
// c0 is a multiple of 8, so the two float4 loads are 32B-aligned.
__device__ __forceinline__ void load_row(const float* __restrict__ row, int c0, float* d) {
    const float4 v0 = *reinterpret_cast<const float4*>(row + c0);
    const float4 v1 = *reinterpret_cast<const float4*>(row + c0 + 4);
    d[1] = v0.x; d[2] = v0.y; d[3] = v0.z; d[4] = v0.w;
    d[5] = v1.x; d[6] = v1.y; d[7] = v1.z; d[8] = v1.w;
    d[0] = row[(c0 == 0) ? 1 : (c0 - 1)];               // reflect col -1 -> 1
    d[9] = row[(c0 + CPT == W) ? (W - 2) : (c0 + CPT)]; // reflect col W -> W-2
}

// Produce output row r for this thread's 8-column strip.
//  pm/pM hold per-column min/max of rows (r-1, r); cur = raw row r.
//  Loads row r+1 into nxt and advances pm/pM to the (r, r+1) pair.
__device__ __forceinline__ void step(const float* __restrict__ base,
                                     float* __restrict__ obase,
                                     int r, int c0,
                                     float* cur, float* nxt,
                                     float* pm, float* pM) {
    int rn = r + 1;
    rn = (rn == H) ? (H - 2) : rn;      // reflect row H -> H-2
    load_row(base + rn * W, c0, nxt);

    float lo[10], hi[10], mid[10];
#pragma unroll
    for (int c = 0; c < 10; ++c) {
        const float n = nxt[c];
        lo[c]  = fminf(pm[c], n);                      // min of column triple
        hi[c]  = fmaxf(pM[c], n);                      // max of column triple
        mid[c] = fmaxf(fminf(pM[c], n), pm[c]);        // mid of column triple
        pm[c]  = fminf(cur[c], n);                     // pair cache for next row
        pM[c]  = fmaxf(cur[c], n);
    }

    float o[CPT];
#pragma unroll
    for (int j = 0; j < CPT; ++j) {
        const float A = fmaxf(fmaxf(lo[j], lo[j + 1]), lo[j + 2]);  // max of mins
        const float C = fminf(fminf(hi[j], hi[j + 1]), hi[j + 2]);  // min of maxes
        const float B = med3f(mid[j], mid[j + 1], mid[j + 2]);      // med of mids
        o[j] = med3f(A, B, C);                                      // exact median9
    }

    float* orow = obase + r * W + c0;
    *reinterpret_cast<float4*>(orow)     = make_float4(o[0], o[1], o[2], o[3]);
    *reinterpret_cast<float4*>(orow + 4) = make_float4(o[4], o[5], o[6], o[7]);
}

__global__ __launch_bounds__(BLOCK)
void MedianFilter_22737556865485_kernel(const float* __restrict__ in,
                                        float* __restrict__ out) {
    const int tid = blockIdx.x * BLOCK + threadIdx.x;
    const int img = tid / THREADS_PER_IMG;
    const int s   = tid % THREADS_PER_IMG;
    const int sx  = s % STRIPS_X;
    const int sy  = s / STRIPS_X;
    const int c0  = sx * CPT;
    const int r0  = sy * ROWS;

    const float* base  = in  + (size_t)img * (H * W);
    float*       obase = out + (size_t)img * (H * W);

    float y[10], z[10], pm[10], pM[10];

    // Prologue: pair (r0-1, r0); reflect row -1 -> 1.
    {
        float t[10];
        const int rm = (r0 == 0) ? 1 : (r0 - 1);
        load_row(base + rm * W, c0, t);
        load_row(base + r0 * W, c0, y);
#pragma unroll
        for (int c = 0; c < 10; ++c) {
            pm[c] = fminf(t[c], y[c]);
            pM[c] = fmaxf(t[c], y[c]);
        }
    }

    // Period-2 register rotation: y and z alternate roles, no copies.
#pragma unroll 1
    for (int i = 0; i < ROWS; i += 2) {
        step(base, obase, r0 + i,     c0, y, z, pm, pM);
        step(base, obase, r0 + i + 1, c0, z, y, pm, pM);
    }
}

extern "C" void kernel_launch(void* const* d_in, const int* in_sizes, int n_in,
                              void* d_out, int out_size) {
    const float* in  = (const float*)d_in[0];
    float*       out = (float*)d_out;
    const int total_threads = NIMG * THREADS_PER_IMG;   // 98304
    MedianFilter_22737556865485_kernel<<<total_threads / BLOCK, BLOCK>>>(in, out);
}